// round 12
// baseline (speedup 1.0000x reference)
#include <cuda_runtime.h>
#include <cuda_fp16.h>
#include <cstdint>
#include <cstddef>

// ---------------------------------------------------------------------------
// Problem constants
// ---------------------------------------------------------------------------
#define NHEADS   12
#define DHEAD    32
#define NTOK     49
#define DIM      384
#define BN_TOTAL 4096
#define TOKENS   (BN_TOTAL * NTOK)   // 200704
#define QKV_COLS 1152

// Scratch (allocation-free rule: device globals)
// qkv stored head-blocked: [(comp*12+head)][token][32]
__device__ __half g_qkvH[(size_t)TOKENS * QKV_COLS];
__device__ __half g_xH[(size_t)TOKENS * DIM];
__device__ __half g_ctxH[(size_t)TOKENS * DIM];
__device__ __half g_wqkvH[(size_t)QKV_COLS * DIM];
__device__ __half g_wprojH[(size_t)DIM * DIM];

// ---------------------------------------------------------------------------
// Common device helpers
// ---------------------------------------------------------------------------
__device__ __forceinline__ void mma_f16(float* d, const uint32_t* a, const uint32_t* b) {
    asm volatile(
        "mma.sync.aligned.m16n8k16.row.col.f32.f16.f16.f32 "
        "{%0,%1,%2,%3}, {%4,%5,%6,%7}, {%8,%9}, {%0,%1,%2,%3};"
        : "+f"(d[0]), "+f"(d[1]), "+f"(d[2]), "+f"(d[3])
        : "r"(a[0]), "r"(a[1]), "r"(a[2]), "r"(a[3]), "r"(b[0]), "r"(b[1]));
}

__device__ __forceinline__ void ldmx4(uint32_t* r, uint32_t addr) {
    asm volatile("ldmatrix.sync.aligned.m8n8.x4.shared.b16 {%0,%1,%2,%3}, [%4];"
        : "=r"(r[0]), "=r"(r[1]), "=r"(r[2]), "=r"(r[3]) : "r"(addr));
}
__device__ __forceinline__ void ldmx4t(uint32_t* r, uint32_t addr) {
    asm volatile("ldmatrix.sync.aligned.m8n8.x4.trans.shared.b16 {%0,%1,%2,%3}, [%4];"
        : "=r"(r[0]), "=r"(r[1]), "=r"(r[2]), "=r"(r[3]) : "r"(addr));
}

__device__ __forceinline__ uint32_t smem_u32(const void* p) {
    uint32_t a;
    asm("{ .reg .u64 t; cvta.to.shared.u64 t, %1; cvt.u32.u64 %0, t; }"
        : "=r"(a) : "l"(p));
    return a;
}

__device__ __forceinline__ uint32_t packh2(float a, float b) {
    half2 h = __floats2half2_rn(a, b);
    return *(uint32_t*)&h;
}

#define CP_ASYNC16(dst, src) \
    asm volatile("cp.async.cg.shared.global [%0], [%1], 16;" :: "r"(dst), "l"(src))
#define CP_COMMIT() asm volatile("cp.async.commit_group;" ::: "memory")
#define CP_WAIT(n)  asm volatile("cp.async.wait_group %0;" :: "n"(n) : "memory")

// ---------------------------------------------------------------------------
// Prep: fp32 -> fp16 RN convert, three arrays in one launch
// ---------------------------------------------------------------------------
__global__ void cvt3_kernel(const float* __restrict__ s0, __half* __restrict__ d0, size_t n0,
                            const float* __restrict__ s1, __half* __restrict__ d1, size_t n1,
                            const float* __restrict__ s2, __half* __restrict__ d2, size_t n2)
{
    const size_t total = n0 + n1 + n2;
    const size_t stride = (size_t)gridDim.x * blockDim.x;
    for (size_t i = (size_t)blockIdx.x * blockDim.x + threadIdx.x; i < total; i += stride) {
        const float* s; __half* d; size_t k;
        if (i < n0)           { s = s0; d = d0; k = i; }
        else if (i < n0 + n1) { s = s1; d = d1; k = i - n0; }
        else                  { s = s2; d = d2; k = i - n0 - n1; }
        float4 v = *((const float4*)s + k);
        *(uint2*)(d + k * 4) = make_uint2(packh2(v.x, v.y), packh2(v.z, v.w));
    }
}

// ---------------------------------------------------------------------------
// 1-term fp16 GEMM (NT): C = A * B^T + bias. Multi-tile blocks (unchanged R11).
// ---------------------------------------------------------------------------
#define GBM 128
#define GBK 64
#define MGRP 4
#define GPITCH 144
#define PL_BYTES (128 * GPITCH)           // 18432
#define BUF_BYTES (2 * PL_BYTES)          // 36864
#define NSTAGE 3
#define SM_GEMM_TOTAL (NSTAGE * BUF_BYTES)   // 110592

__global__ __launch_bounds__(256, 2)
void gemm_1t(const __half* __restrict__ A, const __half* __restrict__ B,
             const float* __restrict__ bias,
             float* __restrict__ Cf, __half* __restrict__ CH,
             int M, int N, int K, int outHalf)
{
    extern __shared__ char sm[];
    const uint32_t smb = smem_u32(sm);

    const int tid  = threadIdx.x;
    const int wid  = tid >> 5;
    const int lane = tid & 31;
    const int g = lane >> 2;
    const int c = lane & 3;
    const int wm = wid & 1;
    const int wn = wid >> 1;

    const int n0 = blockIdx.x * GBM;
    const __half* gB = B + (size_t)n0 * K;
    const __half* gA0 = A + (size_t)blockIdx.y * (MGRP * GBM) * K;

    const int m_idx = lane >> 3;
    const int rin   = lane & 7;
    const uint32_t aRowOff = (uint32_t)(wm * 64 + (m_idx & 1) * 8 + rin) * GPITCH
                           + (uint32_t)(m_idx >> 1) * 16;
    const uint32_t bRowOff = (uint32_t)(wn * 32 + (m_idx >> 1) * 8 + rin) * GPITCH
                           + (uint32_t)(m_idx & 1) * 16;

    float acc[4][4][4];
    #pragma unroll
    for (int i = 0; i < 4; i++)
        #pragma unroll
        for (int j = 0; j < 4; j++)
            #pragma unroll
            for (int r = 0; r < 4; r++) acc[i][j][r] = 0.f;

    const int NK = K / GBK;        // 6
    const int TS = NK * MGRP;      // 24

    int smt = 0, skt = 0;
    auto stage = [&](int s) {
        const __half* gAt = gA0 + (size_t)smt * GBM * K;
        const uint32_t dst = smb + (uint32_t)s * BUF_BYTES;
        const size_t go = (size_t)skt * GBK;
        #pragma unroll
        for (int cc = 0; cc < 4; cc++) {
            const int idx = tid + cc * 256;
            const int row = idx >> 3, pos = idx & 7;
            const uint32_t d = dst + (uint32_t)row * GPITCH + (uint32_t)pos * 16;
            CP_ASYNC16(d + 0 * PL_BYTES, gAt + (size_t)row * K + go + pos * 8);
            CP_ASYNC16(d + 1 * PL_BYTES, gB  + (size_t)row * K + go + pos * 8);
        }
        CP_COMMIT();
        if (++skt == NK) { skt = 0; smt++; }
    };

    stage(0);
    stage(1);

    int cur = 0, nx2 = 2;
    int cmt = 0, ckt = 0;
    for (int s = 0; s < TS; s++) {
        if (s + 1 < TS) { CP_WAIT(1); } else { CP_WAIT(0); }
        __syncthreads();

        if (s + 2 < TS) stage(nx2);

        const uint32_t bufB = smb + (uint32_t)cur * BUF_BYTES;

        #pragma unroll
        for (int ks = 0; ks < 4; ks++) {
            const uint32_t ko = (uint32_t)ks * 32;

            uint32_t bfr[4][2];
            #pragma unroll
            for (int nn = 0; nn < 2; nn++) {
                uint32_t r4[4];
                ldmx4(r4, bufB + PL_BYTES + bRowOff + (uint32_t)nn * 16 * GPITCH + ko);
                bfr[2 * nn][0] = r4[0]; bfr[2 * nn][1] = r4[1];
                bfr[2 * nn + 1][0] = r4[2]; bfr[2 * nn + 1][1] = r4[3];
            }

            uint32_t af[4][4];
            #pragma unroll
            for (int tm = 0; tm < 4; tm++)
                ldmx4(af[tm], bufB + aRowOff + (uint32_t)tm * 16 * GPITCH + ko);

            #pragma unroll
            for (int tm = 0; tm < 4; tm++)
                #pragma unroll
                for (int tn = 0; tn < 4; tn++)
                    mma_f16(acc[tm][tn], af[tm], bfr[tn]);
        }

        if (ckt == NK - 1) {
            const int m0 = (blockIdx.y * MGRP + cmt) * GBM;
            #pragma unroll
            for (int tm = 0; tm < 4; tm++) {
                const int r = m0 + wm * 64 + tm * 16 + g;
                #pragma unroll
                for (int tn = 0; tn < 4; tn++) {
                    const int col = n0 + wn * 32 + tn * 8 + 2 * c;
                    const float b0 = __ldg(&bias[col]);
                    const float b1 = __ldg(&bias[col + 1]);
                    const float o00 = acc[tm][tn][0] + b0, o01 = acc[tm][tn][1] + b1;
                    const float o10 = acc[tm][tn][2] + b0, o11 = acc[tm][tn][3] + b1;
                    if (outHalf) {
                        const size_t hb = (size_t)(col >> 5) * ((size_t)TOKENS * 32)
                                        + (size_t)(col & 31);
                        *(uint32_t*)(CH + hb + (size_t)r * 32)       = packh2(o00, o01);
                        *(uint32_t*)(CH + hb + (size_t)(r + 8) * 32) = packh2(o10, o11);
                    } else {
                        *(float2*)(Cf + (size_t)r * N + col)       = make_float2(o00, o01);
                        *(float2*)(Cf + (size_t)(r + 8) * N + col) = make_float2(o10, o11);
                    }
                    acc[tm][tn][0] = 0.f; acc[tm][tn][1] = 0.f;
                    acc[tm][tn][2] = 0.f; acc[tm][tn][3] = 0.f;
                }
            }
        }
        if (++ckt == NK) { ckt = 0; cmt++; }

        cur = (cur == 2) ? 0 : cur + 1;
        nx2 = (nx2 == 2) ? 0 : nx2 + 1;
    }
}

// ---------------------------------------------------------------------------
// Tensor-core windowed attention (1-term fp16), 12 heads/block (one bn/block),
// double-buffered gathers, P in registers, table-driven softmax (exp2 path).
// 128 threads / 4 warps.
// ---------------------------------------------------------------------------
#define HPB 12
#define VPITCH 40
// per-buffer plane offsets (halves): Q, K, V
#define OFF_Q 0
#define OFF_K 2560
#define OFF_V 5120
#define BUF_HALVES 7680
// tables (offsets in halves)
#define OFF_SRIDX 15360          // int16[49*52] = 2548 -> pad 2560
#define OFF_SMASK 17920          // float[49*52] = 2548 floats = 5096 halves -> pad 5120
#define OFF_SBALL 23040          // float[169*12] = 2028 floats = 4056 halves -> pad 4064
#define SMEM_HALVES 27104
#define SM_ATTN_TOTAL (SMEM_HALVES * 2)   // 54208 bytes

#define LOG2E 1.4426950408889634f

__global__ __launch_bounds__(128)
void attn_mma(const __half* __restrict__ qkvH,
              const float* __restrict__ mask, const float* __restrict__ bias_table,
              __half* __restrict__ ctxH)
{
    extern __shared__ __half sh[];
    const uint32_t smb = smem_u32(sh);
    uint16_t* sridx = (uint16_t*)(sh + OFF_SRIDX);
    float*    smask = (float*)(sh + OFF_SMASK);
    float*    sball = (float*)(sh + OFF_SBALL);

    const int bn  = blockIdx.x;
    const int tid = threadIdx.x;
    const int w    = tid >> 5;
    const int lane = tid & 31;
    const int g    = lane >> 2;
    const int cq   = lane & 3;
    const int m_idx = lane >> 3;
    const int rin   = lane & 7;

    // zero QKV buffer region only (pads must be 0 for LDSM rows 49..63)
    for (int i = tid; i < (2 * BUF_HALVES) / 8; i += 128)
        *(uint4*)(sh + (size_t)i * 8) = make_uint4(0u, 0u, 0u, 0u);
    __syncthreads();

    const size_t tokbase = (size_t)bn * NTOK;

    // coalesced head-slice gather: 3 planes x 49 rows x 4 chunks = 588 x 16B
    auto issue_qkv = [&](int head, int buf) {
        #pragma unroll 1
        for (int e = tid; e < 588; e += 128) {
            const int p  = e / 196;
            const int ch = e - p * 196;
            const int r  = ch >> 2;
            const int c4 = ch & 3;
            const __half* src = qkvH
                + (((size_t)(p * NHEADS + head) * TOKENS + tokbase + r) << 5) + c4 * 8;
            const uint32_t dst = smb + 2u * (uint32_t)(buf * BUF_HALVES + p * 2560
                               + r * VPITCH + c4 * 8);
            CP_ASYNC16(dst, src);
        }
        CP_COMMIT();
    };

    issue_qkv(0, 0);
    issue_qkv(1, 1);

    // ---- build per-block tables (overlaps the cp.async gathers above) ----
    const float* mrow = mask + (size_t)(bn >> 6) * (NTOK * NTOK);
    for (int idx = tid; idx < NTOK * 52; idx += 128) {
        const int i = idx / 52, j = idx - (idx / 52) * 52;
        if (j < NTOK) {
            const int ih = i / 7, iw = i - ih * 7;
            const int jh = j / 7, jw = j - jh * 7;
            sridx[idx] = (uint16_t)((ih - jh + 6) * 13 + (iw - jw + 6));
            smask[idx] = __ldg(&mrow[i * NTOK + j]) * LOG2E;
        } else {
            sridx[idx] = 0;
            smask[idx] = 0.f;
        }
    }
    for (int e = tid; e < 169 * NHEADS; e += 128)
        sball[e] = __ldg(&bias_table[e]) * LOG2E;   // layout [ridx][h]

    const float SC = 0.17677669529663687f * LOG2E;  // scale * log2e

    for (int t = 0; t < HPB; t++) {
        const int h   = t;
        const uint32_t bofs = (uint32_t)((t & 1) * BUF_HALVES);

        if (t < HPB - 1) { CP_WAIT(1); } else { CP_WAIT(0); }
        __syncthreads();

        // ---- QK^T ----
        float acc[7][4];
        #pragma unroll
        for (int nt = 0; nt < 7; nt++)
            #pragma unroll
            for (int r = 0; r < 4; r++) acc[nt][r] = 0.f;

        uint32_t qf[2][4];
        #pragma unroll
        for (int kt = 0; kt < 2; kt++) {
            const uint32_t a = smb + 2u * (uint32_t)(bofs + OFF_Q
                             + (16 * w + (m_idx & 1) * 8 + rin) * VPITCH
                             + (m_idx >> 1) * 8 + kt * 16);
            ldmx4(qf[kt], a);
        }

        #pragma unroll
        for (int kt = 0; kt < 2; kt++)
            #pragma unroll
            for (int p = 0; p < 4; p++) {
                uint32_t r4[4];
                const uint32_t a = smb + 2u * (uint32_t)(bofs + OFF_K
                                 + (16 * p + (m_idx >> 1) * 8 + rin) * VPITCH
                                 + (m_idx & 1) * 8 + kt * 16);
                ldmx4(r4, a);
                uint32_t b0[2] = { r4[0], r4[1] };
                uint32_t b1[2] = { r4[2], r4[3] };
                mma_f16(acc[2 * p], qf[kt], b0);
                if (p < 3) mma_f16(acc[2 * p + 1], qf[kt], b1);
            }

        // ---- softmax in fragments (table-driven, exp2) ----
        const int i0 = 16 * w + g, i1 = i0 + 8;

        float mm0 = -1e30f, mm1 = -1e30f;
        #pragma unroll
        for (int nt = 0; nt < 7; nt++) {
            #pragma unroll
            for (int r = 0; r < 4; r++) {
                const int i = (r < 2) ? i0 : i1;
                const int j = 8 * nt + 2 * cq + (r & 1);
                float s;
                if (i >= NTOK) s = 0.f;
                else if (j >= NTOK) s = -1e30f;
                else {
                    const int e = i * 52 + j;
                    s = acc[nt][r] * SC + sball[(int)sridx[e] * NHEADS + h] + smask[e];
                }
                acc[nt][r] = s;
                if (r < 2) mm0 = fmaxf(mm0, s); else mm1 = fmaxf(mm1, s);
            }
        }
        mm0 = fmaxf(mm0, __shfl_xor_sync(0xffffffffu, mm0, 1));
        mm0 = fmaxf(mm0, __shfl_xor_sync(0xffffffffu, mm0, 2));
        mm1 = fmaxf(mm1, __shfl_xor_sync(0xffffffffu, mm1, 1));
        mm1 = fmaxf(mm1, __shfl_xor_sync(0xffffffffu, mm1, 2));

        float s0 = 0.f, s1 = 0.f;
        #pragma unroll
        for (int nt = 0; nt < 7; nt++) {
            #pragma unroll
            for (int r = 0; r < 4; r++) {
                const float e = exp2f(acc[nt][r] - ((r < 2) ? mm0 : mm1));
                if (r < 2) s0 += e; else s1 += e;
                acc[nt][r] = e;
            }
        }
        s0 += __shfl_xor_sync(0xffffffffu, s0, 1);
        s0 += __shfl_xor_sync(0xffffffffu, s0, 2);
        s1 += __shfl_xor_sync(0xffffffffu, s1, 1);
        s1 += __shfl_xor_sync(0xffffffffu, s1, 2);
        const float inv0 = 1.f / s0;
        const float inv1 = 1.f / s1;

        // ---- PV: P fragments built directly from acc registers ----
        float pv[4][4];
        #pragma unroll
        for (int nt = 0; nt < 4; nt++)
            #pragma unroll
            for (int r = 0; r < 4; r++) pv[nt][r] = 0.f;

        #pragma unroll
        for (int kt = 0; kt < 4; kt++) {
            uint32_t pf[4];
            pf[0] = packh2(acc[2 * kt][0], acc[2 * kt][1]);
            pf[1] = packh2(acc[2 * kt][2], acc[2 * kt][3]);
            if (2 * kt + 1 < 7) {
                pf[2] = packh2(acc[2 * kt + 1][0], acc[2 * kt + 1][1]);
                pf[3] = packh2(acc[2 * kt + 1][2], acc[2 * kt + 1][3]);
            } else {
                pf[2] = 0u; pf[3] = 0u;
            }
            #pragma unroll
            for (int dp = 0; dp < 2; dp++) {
                uint32_t vf[4];
                const uint32_t a = smb + 2u * (uint32_t)(bofs + OFF_V
                                 + (16 * kt + (m_idx & 1) * 8 + rin) * VPITCH
                                 + (m_idx >> 1) * 8 + dp * 16);
                ldmx4t(vf, a);
                uint32_t b0[2] = { vf[0], vf[1] };
                uint32_t b1[2] = { vf[2], vf[3] };
                mma_f16(pv[2 * dp], pf, b0);
                mma_f16(pv[2 * dp + 1], pf, b1);
            }
        }

        // ---- epilogue: normalize, store ctx fp16 ----
        const size_t ob = (size_t)bn * NTOK * DIM + (size_t)h * DHEAD;
        if (i0 < NTOK) {
            #pragma unroll
            for (int nt = 0; nt < 4; nt++) {
                const int d = 8 * nt + 2 * cq;
                *(uint32_t*)(ctxH + ob + (size_t)i0 * DIM + d)
                    = packh2(pv[nt][0] * inv0, pv[nt][1] * inv0);
            }
        }
        if (i1 < NTOK) {
            #pragma unroll
            for (int nt = 0; nt < 4; nt++) {
                const int d = 8 * nt + 2 * cq;
                *(uint32_t*)(ctxH + ob + (size_t)i1 * DIM + d)
                    = packh2(pv[nt][2] * inv1, pv[nt][3] * inv1);
            }
        }

        __syncthreads();   // all reads of buffer done

        if (t + 2 < HPB) issue_qkv(t + 2, t & 1);
    }
}

// ---------------------------------------------------------------------------
extern "C" void kernel_launch(void* const* d_in, const int* in_sizes, int n_in,
                              void* d_out, int out_size)
{
    const float* x          = (const float*)d_in[0];
    const float* mask       = (const float*)d_in[1];
    const float* w_qkv      = (const float*)d_in[2];
    const float* b_qkv      = (const float*)d_in[3];
    const float* w_proj     = (const float*)d_in[4];
    const float* b_proj     = (const float*)d_in[5];
    const float* bias_table = (const float*)d_in[6];
    float* out = (float*)d_out;

    __half *qkvH, *xH, *ctxH, *wqH, *wpH;
    cudaGetSymbolAddress((void**)&qkvH, g_qkvH);
    cudaGetSymbolAddress((void**)&xH,   g_xH);
    cudaGetSymbolAddress((void**)&ctxH, g_ctxH);
    cudaGetSymbolAddress((void**)&wqH,  g_wqkvH);
    cudaGetSymbolAddress((void**)&wpH,  g_wprojH);

    cudaFuncSetAttribute(gemm_1t, cudaFuncAttributeMaxDynamicSharedMemorySize, SM_GEMM_TOTAL);
    cudaFuncSetAttribute(attn_mma, cudaFuncAttributeMaxDynamicSharedMemorySize, SM_ATTN_TOTAL);

    // 0) prep: fp16 RN converts (single launch)
    cvt3_kernel<<<1480, 256>>>(x, xH, (size_t)TOKENS * DIM / 4,
                               w_qkv, wqH, (size_t)QKV_COLS * DIM / 4,
                               w_proj, wpH, (size_t)DIM * DIM / 4);

    // 1) QKV projection -> head-blocked fp16
    {
        dim3 grid(QKV_COLS / 128, TOKENS / (128 * MGRP));
        gemm_1t<<<grid, 256, SM_GEMM_TOTAL>>>(xH, wqH, b_qkv, nullptr, qkvH,
                                              TOKENS, QKV_COLS, DIM, 1);
    }
    // 2) tensor-core windowed attention (12 heads/block)
    attn_mma<<<BN_TOTAL, 128, SM_ATTN_TOTAL>>>(qkvH, mask, bias_table, ctxH);
    // 3) output projection -> fp32 out
    {
        dim3 grid(DIM / 128, TOKENS / (128 * MGRP));
        gemm_1t<<<grid, 256, SM_GEMM_TOTAL>>>(ctxH, wpH, b_proj, out, nullptr,
                                              TOKENS, DIM, DIM, 0);
    }
}

// round 13
// speedup vs baseline: 1.1548x; 1.1548x over previous
#include <cuda_runtime.h>
#include <cuda_fp16.h>
#include <cstdint>
#include <cstddef>

// ---------------------------------------------------------------------------
// Problem constants
// ---------------------------------------------------------------------------
#define NHEADS   12
#define DHEAD    32
#define NTOK     49
#define DIM      384
#define BN_TOTAL 4096
#define TOKENS   (BN_TOTAL * NTOK)   // 200704
#define QKV_COLS 1152

// Scratch (allocation-free rule: device globals)
// qkv stored head-blocked: [(comp*12+head)][token][32]
__device__ __half g_qkvH[(size_t)TOKENS * QKV_COLS];
__device__ __half g_xH[(size_t)TOKENS * DIM];
__device__ __half g_ctxH[(size_t)TOKENS * DIM];
__device__ __half g_wqkvH[(size_t)QKV_COLS * DIM];
__device__ __half g_wprojH[(size_t)DIM * DIM];

// ---------------------------------------------------------------------------
// Common device helpers
// ---------------------------------------------------------------------------
__device__ __forceinline__ void mma_f16(float* d, const uint32_t* a, const uint32_t* b) {
    asm volatile(
        "mma.sync.aligned.m16n8k16.row.col.f32.f16.f16.f32 "
        "{%0,%1,%2,%3}, {%4,%5,%6,%7}, {%8,%9}, {%0,%1,%2,%3};"
        : "+f"(d[0]), "+f"(d[1]), "+f"(d[2]), "+f"(d[3])
        : "r"(a[0]), "r"(a[1]), "r"(a[2]), "r"(a[3]), "r"(b[0]), "r"(b[1]));
}

__device__ __forceinline__ void ldmx4(uint32_t* r, uint32_t addr) {
    asm volatile("ldmatrix.sync.aligned.m8n8.x4.shared.b16 {%0,%1,%2,%3}, [%4];"
        : "=r"(r[0]), "=r"(r[1]), "=r"(r[2]), "=r"(r[3]) : "r"(addr));
}
__device__ __forceinline__ void ldmx4t(uint32_t* r, uint32_t addr) {
    asm volatile("ldmatrix.sync.aligned.m8n8.x4.trans.shared.b16 {%0,%1,%2,%3}, [%4];"
        : "=r"(r[0]), "=r"(r[1]), "=r"(r[2]), "=r"(r[3]) : "r"(addr));
}

__device__ __forceinline__ uint32_t smem_u32(const void* p) {
    uint32_t a;
    asm("{ .reg .u64 t; cvta.to.shared.u64 t, %1; cvt.u32.u64 %0, t; }"
        : "=r"(a) : "l"(p));
    return a;
}

__device__ __forceinline__ uint32_t packh2(float a, float b) {
    half2 h = __floats2half2_rn(a, b);
    return *(uint32_t*)&h;
}

#define CP_ASYNC16(dst, src) \
    asm volatile("cp.async.cg.shared.global [%0], [%1], 16;" :: "r"(dst), "l"(src))
#define CP_COMMIT() asm volatile("cp.async.commit_group;" ::: "memory")
#define CP_WAIT(n)  asm volatile("cp.async.wait_group %0;" :: "n"(n) : "memory")

// ---------------------------------------------------------------------------
// Prep: fp32 -> fp16 RN convert, three arrays in one launch
// ---------------------------------------------------------------------------
__global__ void cvt3_kernel(const float* __restrict__ s0, __half* __restrict__ d0, size_t n0,
                            const float* __restrict__ s1, __half* __restrict__ d1, size_t n1,
                            const float* __restrict__ s2, __half* __restrict__ d2, size_t n2)
{
    const size_t total = n0 + n1 + n2;
    const size_t stride = (size_t)gridDim.x * blockDim.x;
    for (size_t i = (size_t)blockIdx.x * blockDim.x + threadIdx.x; i < total; i += stride) {
        const float* s; __half* d; size_t k;
        if (i < n0)           { s = s0; d = d0; k = i; }
        else if (i < n0 + n1) { s = s1; d = d1; k = i - n0; }
        else                  { s = s2; d = d2; k = i - n0 - n1; }
        float4 v = *((const float4*)s + k);
        *(uint2*)(d + k * 4) = make_uint2(packh2(v.x, v.y), packh2(v.z, v.w));
    }
}

// ---------------------------------------------------------------------------
// 1-term fp16 GEMM (NT): C = A * B^T + bias. Multi-tile blocks, K templated
// so the mainloop fully unrolls (compile-time addresses, pipelined LDSM).
// BM=BN=128, BK=64, 3-stage cp.async, 256 threads, 2 CTAs/SM.
// ---------------------------------------------------------------------------
#define GBM 128
#define GBK 64
#define MGRP 4
#define GPITCH 144
#define PL_BYTES (128 * GPITCH)           // 18432
#define BUF_BYTES (2 * PL_BYTES)          // 36864
#define NSTAGE 3
#define SM_GEMM_TOTAL (NSTAGE * BUF_BYTES)   // 110592

template<int K, int OUTHALF>
__global__ __launch_bounds__(256, 2)
void gemm_1t(const __half* __restrict__ A, const __half* __restrict__ B,
             const float* __restrict__ bias,
             float* __restrict__ Cf, __half* __restrict__ CH, int N)
{
    extern __shared__ char sm[];
    const uint32_t smb = smem_u32(sm);

    const int tid  = threadIdx.x;
    const int wid  = tid >> 5;
    const int lane = tid & 31;
    const int g = lane >> 2;
    const int c = lane & 3;
    const int wm = wid & 1;
    const int wn = wid >> 1;

    const int n0 = blockIdx.x * GBM;
    const __half* gB = B + (size_t)n0 * K;
    const __half* gA0 = A + (size_t)blockIdx.y * (MGRP * GBM) * K;

    const int m_idx = lane >> 3;
    const int rin   = lane & 7;
    const uint32_t aRowOff = (uint32_t)(wm * 64 + (m_idx & 1) * 8 + rin) * GPITCH
                           + (uint32_t)(m_idx >> 1) * 16;
    const uint32_t bRowOff = (uint32_t)(wn * 32 + (m_idx >> 1) * 8 + rin) * GPITCH
                           + (uint32_t)(m_idx & 1) * 16;

    float acc[4][4][4];
    #pragma unroll
    for (int i = 0; i < 4; i++)
        #pragma unroll
        for (int j = 0; j < 4; j++)
            #pragma unroll
            for (int r = 0; r < 4; r++) acc[i][j][r] = 0.f;

    constexpr int NK = K / GBK;        // 6
    constexpr int TS = NK * MGRP;      // 24

    // stage k-chunk (smt, skt) into smem stage s
    auto stage = [&](int s, int smt, int skt) {
        const __half* gAt = gA0 + (size_t)smt * GBM * K;
        const uint32_t dst = smb + (uint32_t)s * BUF_BYTES;
        const int go = skt * GBK;
        #pragma unroll
        for (int cc = 0; cc < 4; cc++) {
            const int idx = tid + cc * 256;
            const int row = idx >> 3, pos = idx & 7;
            const uint32_t d = dst + (uint32_t)row * GPITCH + (uint32_t)pos * 16;
            CP_ASYNC16(d + 0 * PL_BYTES, gAt + (size_t)row * K + go + pos * 8);
            CP_ASYNC16(d + 1 * PL_BYTES, gB  + (size_t)row * K + go + pos * 8);
        }
        CP_COMMIT();
    };

    stage(0, 0, 0);
    stage(1, 0, 1);

    #pragma unroll
    for (int s = 0; s < TS; s++) {
        if (s + 1 < TS) { CP_WAIT(1); } else { CP_WAIT(0); }
        __syncthreads();

        if (s + 2 < TS) stage((s + 2) % NSTAGE, (s + 2) / NK, (s + 2) % NK);

        const uint32_t bufB = smb + (uint32_t)(s % NSTAGE) * BUF_BYTES;

        #pragma unroll
        for (int ks = 0; ks < 4; ks++) {
            const uint32_t ko = (uint32_t)ks * 32;

            uint32_t bfr[4][2];
            #pragma unroll
            for (int nn = 0; nn < 2; nn++) {
                uint32_t r4[4];
                ldmx4(r4, bufB + PL_BYTES + bRowOff + (uint32_t)nn * 16 * GPITCH + ko);
                bfr[2 * nn][0] = r4[0]; bfr[2 * nn][1] = r4[1];
                bfr[2 * nn + 1][0] = r4[2]; bfr[2 * nn + 1][1] = r4[3];
            }

            uint32_t af[4][4];
            #pragma unroll
            for (int tm = 0; tm < 4; tm++)
                ldmx4(af[tm], bufB + aRowOff + (uint32_t)tm * 16 * GPITCH + ko);

            #pragma unroll
            for (int tm = 0; tm < 4; tm++)
                #pragma unroll
                for (int tn = 0; tn < 4; tn++)
                    mma_f16(acc[tm][tn], af[tm], bfr[tn]);
        }

        if ((s % NK) == NK - 1) {
            const int cmt = s / NK;
            const int m0 = (blockIdx.y * MGRP + cmt) * GBM;
            #pragma unroll
            for (int tm = 0; tm < 4; tm++) {
                const int r = m0 + wm * 64 + tm * 16 + g;
                #pragma unroll
                for (int tn = 0; tn < 4; tn++) {
                    const int col = n0 + wn * 32 + tn * 8 + 2 * c;
                    const float b0 = __ldg(&bias[col]);
                    const float b1 = __ldg(&bias[col + 1]);
                    const float o00 = acc[tm][tn][0] + b0, o01 = acc[tm][tn][1] + b1;
                    const float o10 = acc[tm][tn][2] + b0, o11 = acc[tm][tn][3] + b1;
                    if (OUTHALF) {
                        const size_t hb = (size_t)(col >> 5) * ((size_t)TOKENS * 32)
                                        + (size_t)(col & 31);
                        *(uint32_t*)(CH + hb + (size_t)r * 32)       = packh2(o00, o01);
                        *(uint32_t*)(CH + hb + (size_t)(r + 8) * 32) = packh2(o10, o11);
                    } else {
                        *(float2*)(Cf + (size_t)r * N + col)       = make_float2(o00, o01);
                        *(float2*)(Cf + (size_t)(r + 8) * N + col) = make_float2(o10, o11);
                    }
                    acc[tm][tn][0] = 0.f; acc[tm][tn][1] = 0.f;
                    acc[tm][tn][2] = 0.f; acc[tm][tn][3] = 0.f;
                }
            }
        }
    }
}

// ---------------------------------------------------------------------------
// Tensor-core windowed attention (R11 structure), 6 heads/block, 128 threads,
// double-buffered gathers, P in registers, exp2/log2e softmax path.
// ---------------------------------------------------------------------------
#define HPB 6
#define VPITCH 40
#define OFF_Q 0
#define OFF_K 2560
#define OFF_V 5120
#define BUF_HALVES 7680
#define OFF_SBIAS 15360          // 169 floats = 338 halves
#define SMEM_HALVES 15704
#define SM_ATTN_TOTAL (SMEM_HALVES * 2)   // 31408 bytes

#define LOG2E 1.4426950408889634f

__global__ __launch_bounds__(128)
void attn_mma(const __half* __restrict__ qkvH,
              const float* __restrict__ mask, const float* __restrict__ bias_table,
              __half* __restrict__ ctxH)
{
    extern __shared__ __half sh[];
    const uint32_t smb = smem_u32(sh);
    float* sbias = (float*)(sh + OFF_SBIAS);

    const int blk   = blockIdx.x;
    const int bn    = blk >> 1;
    const int hbase = (blk & 1) * HPB;
    const int tid = threadIdx.x;
    const int w    = tid >> 5;
    const int lane = tid & 31;
    const int g    = lane >> 2;
    const int cq   = lane & 3;
    const int m_idx = lane >> 3;
    const int rin   = lane & 7;

    // zero all smem once (pads must be 0)
    for (int i = tid; i < SMEM_HALVES / 8; i += 128)
        *(uint4*)(sh + (size_t)i * 8) = make_uint4(0u, 0u, 0u, 0u);
    __syncthreads();

    const size_t tokbase = (size_t)bn * NTOK;

    // coalesced head-slice gather: 3 planes x 49 rows x 4 chunks = 588 x 16B
    auto issue_qkv = [&](int head, int buf) {
        #pragma unroll 1
        for (int e = tid; e < 588; e += 128) {
            const int p  = e / 196;
            const int ch = e - p * 196;
            const int r  = ch >> 2;
            const int c4 = ch & 3;
            const __half* src = qkvH
                + (((size_t)(p * NHEADS + head) * TOKENS + tokbase + r) << 5) + c4 * 8;
            const uint32_t dst = smb + 2u * (uint32_t)(buf * BUF_HALVES + p * 2560
                               + r * VPITCH + c4 * 8);
            CP_ASYNC16(dst, src);
        }
        CP_COMMIT();
    };

    issue_qkv(hbase + 0, 0);
    issue_qkv(hbase + 1, 1);

    const float SC = 0.17677669529663687f * LOG2E;
    const float* mrow = mask + (size_t)(bn >> 6) * (NTOK * NTOK);

    for (int t = 0; t < HPB; t++) {
        const int h   = hbase + t;
        const uint32_t bofs = (uint32_t)((t & 1) * BUF_HALVES);

        if (t < HPB - 1) { CP_WAIT(1); } else { CP_WAIT(0); }
        for (int e = tid; e < 169; e += 128)
            sbias[e] = bias_table[e * NHEADS + h] * LOG2E;
        __syncthreads();

        // ---- QK^T ----
        float acc[7][4];
        #pragma unroll
        for (int nt = 0; nt < 7; nt++)
            #pragma unroll
            for (int r = 0; r < 4; r++) acc[nt][r] = 0.f;

        uint32_t qf[2][4];
        #pragma unroll
        for (int kt = 0; kt < 2; kt++) {
            const uint32_t a = smb + 2u * (uint32_t)(bofs + OFF_Q
                             + (16 * w + (m_idx & 1) * 8 + rin) * VPITCH
                             + (m_idx >> 1) * 8 + kt * 16);
            ldmx4(qf[kt], a);
        }

        #pragma unroll
        for (int kt = 0; kt < 2; kt++)
            #pragma unroll
            for (int p = 0; p < 4; p++) {
                uint32_t r4[4];
                const uint32_t a = smb + 2u * (uint32_t)(bofs + OFF_K
                                 + (16 * p + (m_idx >> 1) * 8 + rin) * VPITCH
                                 + (m_idx & 1) * 8 + kt * 16);
                ldmx4(r4, a);
                uint32_t b0[2] = { r4[0], r4[1] };
                uint32_t b1[2] = { r4[2], r4[3] };
                mma_f16(acc[2 * p], qf[kt], b0);
                if (p < 3) mma_f16(acc[2 * p + 1], qf[kt], b1);
            }

        // ---- softmax in fragments (exp2 path) ----
        const int i0 = 16 * w + g, i1 = i0 + 8;

        float mm0 = -1e30f, mm1 = -1e30f;
        #pragma unroll
        for (int nt = 0; nt < 7; nt++) {
            #pragma unroll
            for (int r = 0; r < 4; r++) {
                const int i = (r < 2) ? i0 : i1;
                const int j = 8 * nt + 2 * cq + (r & 1);
                float s;
                if (i >= NTOK) s = 0.f;
                else if (j >= NTOK) s = -1e30f;
                else {
                    const int ih = i / 7, iw = i - ih * 7;
                    const int jh = j / 7, jw = j - jh * 7;
                    const int ridx = (ih - jh + 6) * 13 + (iw - jw + 6);
                    s = fmaf(acc[nt][r], SC,
                             fmaf(__ldg(&mrow[i * NTOK + j]), LOG2E, sbias[ridx]));
                }
                acc[nt][r] = s;
                if (r < 2) mm0 = fmaxf(mm0, s); else mm1 = fmaxf(mm1, s);
            }
        }
        mm0 = fmaxf(mm0, __shfl_xor_sync(0xffffffffu, mm0, 1));
        mm0 = fmaxf(mm0, __shfl_xor_sync(0xffffffffu, mm0, 2));
        mm1 = fmaxf(mm1, __shfl_xor_sync(0xffffffffu, mm1, 1));
        mm1 = fmaxf(mm1, __shfl_xor_sync(0xffffffffu, mm1, 2));

        float s0 = 0.f, s1 = 0.f;
        #pragma unroll
        for (int nt = 0; nt < 7; nt++) {
            #pragma unroll
            for (int r = 0; r < 4; r++) {
                const float e = exp2f(acc[nt][r] - ((r < 2) ? mm0 : mm1));
                if (r < 2) s0 += e; else s1 += e;
                acc[nt][r] = e;
            }
        }
        s0 += __shfl_xor_sync(0xffffffffu, s0, 1);
        s0 += __shfl_xor_sync(0xffffffffu, s0, 2);
        s1 += __shfl_xor_sync(0xffffffffu, s1, 1);
        s1 += __shfl_xor_sync(0xffffffffu, s1, 2);
        const float inv0 = 1.f / s0;
        const float inv1 = 1.f / s1;

        // ---- PV: P fragments built directly from acc registers ----
        float pv[4][4];
        #pragma unroll
        for (int nt = 0; nt < 4; nt++)
            #pragma unroll
            for (int r = 0; r < 4; r++) pv[nt][r] = 0.f;

        #pragma unroll
        for (int kt = 0; kt < 4; kt++) {
            uint32_t pf[4];
            pf[0] = packh2(acc[2 * kt][0], acc[2 * kt][1]);
            pf[1] = packh2(acc[2 * kt][2], acc[2 * kt][3]);
            if (2 * kt + 1 < 7) {
                pf[2] = packh2(acc[2 * kt + 1][0], acc[2 * kt + 1][1]);
                pf[3] = packh2(acc[2 * kt + 1][2], acc[2 * kt + 1][3]);
            } else {
                pf[2] = 0u; pf[3] = 0u;
            }
            #pragma unroll
            for (int dp = 0; dp < 2; dp++) {
                uint32_t vf[4];
                const uint32_t a = smb + 2u * (uint32_t)(bofs + OFF_V
                                 + (16 * kt + (m_idx & 1) * 8 + rin) * VPITCH
                                 + (m_idx >> 1) * 8 + dp * 16);
                ldmx4t(vf, a);
                uint32_t b0[2] = { vf[0], vf[1] };
                uint32_t b1[2] = { vf[2], vf[3] };
                mma_f16(pv[2 * dp], pf, b0);
                mma_f16(pv[2 * dp + 1], pf, b1);
            }
        }

        // ---- epilogue: normalize, store ctx fp16 ----
        const size_t ob = (size_t)bn * NTOK * DIM + (size_t)h * DHEAD;
        if (i0 < NTOK) {
            #pragma unroll
            for (int nt = 0; nt < 4; nt++) {
                const int d = 8 * nt + 2 * cq;
                *(uint32_t*)(ctxH + ob + (size_t)i0 * DIM + d)
                    = packh2(pv[nt][0] * inv0, pv[nt][1] * inv0);
            }
        }
        if (i1 < NTOK) {
            #pragma unroll
            for (int nt = 0; nt < 4; nt++) {
                const int d = 8 * nt + 2 * cq;
                *(uint32_t*)(ctxH + ob + (size_t)i1 * DIM + d)
                    = packh2(pv[nt][2] * inv1, pv[nt][3] * inv1);
            }
        }

        __syncthreads();   // all reads of buffer + sbias done

        if (t + 2 < HPB) issue_qkv(hbase + t + 2, t & 1);
    }
}

// ---------------------------------------------------------------------------
extern "C" void kernel_launch(void* const* d_in, const int* in_sizes, int n_in,
                              void* d_out, int out_size)
{
    const float* x          = (const float*)d_in[0];
    const float* mask       = (const float*)d_in[1];
    const float* w_qkv      = (const float*)d_in[2];
    const float* b_qkv      = (const float*)d_in[3];
    const float* w_proj     = (const float*)d_in[4];
    const float* b_proj     = (const float*)d_in[5];
    const float* bias_table = (const float*)d_in[6];
    float* out = (float*)d_out;

    __half *qkvH, *xH, *ctxH, *wqH, *wpH;
    cudaGetSymbolAddress((void**)&qkvH, g_qkvH);
    cudaGetSymbolAddress((void**)&xH,   g_xH);
    cudaGetSymbolAddress((void**)&ctxH, g_ctxH);
    cudaGetSymbolAddress((void**)&wqH,  g_wqkvH);
    cudaGetSymbolAddress((void**)&wpH,  g_wprojH);

    cudaFuncSetAttribute(gemm_1t<384, 1>, cudaFuncAttributeMaxDynamicSharedMemorySize, SM_GEMM_TOTAL);
    cudaFuncSetAttribute(gemm_1t<384, 0>, cudaFuncAttributeMaxDynamicSharedMemorySize, SM_GEMM_TOTAL);
    cudaFuncSetAttribute(attn_mma, cudaFuncAttributeMaxDynamicSharedMemorySize, SM_ATTN_TOTAL);

    // 0) prep: fp16 RN converts (single launch)
    cvt3_kernel<<<1480, 256>>>(x, xH, (size_t)TOKENS * DIM / 4,
                               w_qkv, wqH, (size_t)QKV_COLS * DIM / 4,
                               w_proj, wpH, (size_t)DIM * DIM / 4);

    // 1) QKV projection -> head-blocked fp16
    {
        dim3 grid(QKV_COLS / 128, TOKENS / (128 * MGRP));
        gemm_1t<384, 1><<<grid, 256, SM_GEMM_TOTAL>>>(xH, wqH, b_qkv, nullptr, qkvH,
                                                      QKV_COLS);
    }
    // 2) tensor-core windowed attention (6 heads/block, R11 structure)
    attn_mma<<<BN_TOTAL * 2, 128, SM_ATTN_TOTAL>>>(qkvH, mask, bias_table, ctxH);
    // 3) output projection -> fp32 out
    {
        dim3 grid(DIM / 128, TOKENS / (128 * MGRP));
        gemm_1t<384, 0><<<grid, 256, SM_GEMM_TOTAL>>>(ctxH, wpH, b_proj, out, nullptr,
                                                      DIM);
    }
}